// round 1
// baseline (speedup 1.0000x reference)
#include <cuda_runtime.h>
#include <cstdint>

// ---------------------------------------------------------------------------
// Problem constants (from reference): b=8, t=16, c=64, h=w=56
//   DIM=8 (pool grid), ph=pw=7, token dim = 64, DIM_HEAD=64, scale=0.125
// ---------------------------------------------------------------------------
#define B_    8
#define T_    16
#define C_    64
#define HW_   3136            // 56*56
#define ROWB  12544           // HW_*4 bytes
#define NTOK  64              // DIM*DIM
#define LN_EPS 1e-5f
#define SCALE  0.125f         // 64^-0.5

// Shared-memory layout (float indices)
#define SM_V     0            // 16*3136 = 50176 floats  (v tile, raw x slice)
#define SM_M     50176        // 4096 floats (W_q W_k^T)
#define SM_S     54272        // 1024 floats (tokens s, then normalized in place)
#define SM_U     55296        // 1024 floats (u = s_n @ M)
#define SM_G     56320        // 64 gamma
#define SM_BE    56384        // 64 beta
#define SM_DOTS  56448        // 256
#define SM_ATT2  56704        // 512 (attn duplicated into f32x2 pairs)
#define SM_MU    57216        // 16
#define SM_RSTD  57232        // 16
#define SM_MBAR  57248        // 2 floats = 8B mbarrier
#define SMEM_BYTES 229376     // >= 57250*4, < 232448 opt-in limit

// Global scratch for M (precomputed once per launch by a tiny kernel)
__device__ float g_M[64 * 64];

// ---------------------------------------------------------------------------
// PTX helpers
// ---------------------------------------------------------------------------
__device__ __forceinline__ uint32_t smem_u32(const void* p) {
    uint32_t a;
    asm("{ .reg .u64 t; cvta.to.shared.u64 t, %1; cvt.u32.u64 %0, t; }"
        : "=r"(a) : "l"(p));
    return a;
}

__device__ __forceinline__ unsigned long long fma2(unsigned long long a,
                                                   unsigned long long b,
                                                   unsigned long long c) {
    unsigned long long d;
    asm("fma.rn.f32x2 %0, %1, %2, %3;" : "=l"(d) : "l"(a), "l"(b), "l"(c));
    return d;
}

__device__ __forceinline__ void mbar_init(uint32_t addr, uint32_t count) {
    asm volatile("mbarrier.init.shared.b64 [%0], %1;" :: "r"(addr), "r"(count) : "memory");
}
__device__ __forceinline__ void mbar_expect_tx(uint32_t addr, uint32_t bytes) {
    asm volatile("mbarrier.arrive.expect_tx.shared.b64 _, [%0], %1;"
                 :: "r"(addr), "r"(bytes) : "memory");
}
__device__ __forceinline__ void bulk_g2s(uint32_t dst, const void* src,
                                         uint32_t bytes, uint32_t mbar) {
    asm volatile(
        "cp.async.bulk.shared::cta.global.mbarrier::complete_tx::bytes [%0], [%1], %2, [%3];"
        :: "r"(dst), "l"(src), "r"(bytes), "r"(mbar) : "memory");
}
__device__ __forceinline__ void mbar_wait(uint32_t addr, uint32_t parity) {
    asm volatile(
        "{\n\t"
        ".reg .pred P;\n\t"
        "LAB_W%=:\n\t"
        "mbarrier.try_wait.parity.acquire.cta.shared::cta.b64 P, [%0], %1, 0x989680;\n\t"
        "@P bra.uni LAB_D%=;\n\t"
        "bra.uni LAB_W%=;\n\t"
        "LAB_D%=:\n\t"
        "}"
        :: "r"(addr), "r"(parity) : "memory");
}

// ---------------------------------------------------------------------------
// Kernel 1: M = W_q @ W_k^T   (64x64, shared across all 512 tiles)
//   W_qk stored (in=64, out=128): q cols [0,64), k cols [64,128)
//   M[e][e2] = sum_d W[e][d] * W[e2][64+d]
// ---------------------------------------------------------------------------
__global__ void precompute_M(const float* __restrict__ W) {
    int idx = blockIdx.x * blockDim.x + threadIdx.x;   // 0..4095
    int e  = idx >> 6;
    int e2 = idx & 63;
    float acc = 0.f;
#pragma unroll
    for (int d = 0; d < 64; d++)
        acc = fmaf(W[e * 128 + d], W[e2 * 128 + 64 + d], acc);
    g_M[idx] = acc;
}

// ---------------------------------------------------------------------------
// Kernel 2: one CTA per (b,c) pair. Entire x[b,:,c,:,:] slice lives in SMEM.
//   pool -> +pos -> LN -> dots = s_n M s_n^T * scale -> softmax -> attn@v + v
// ---------------------------------------------------------------------------
extern __shared__ float smem[];

__global__ void __launch_bounds__(1024, 1)
cta_fused(const float* __restrict__ x,
          const float* __restrict__ pos,
          const float* __restrict__ gamma,
          const float* __restrict__ beta,
          float* __restrict__ out) {
    const int bc  = blockIdx.x;        // = b*64 + c
    const int b   = bc >> 6;
    const int c   = bc & 63;
    const int tid = threadIdx.x;

    float* v    = smem + SM_V;
    float* Msh  = smem + SM_M;
    float* s    = smem + SM_S;
    float* u    = smem + SM_U;
    float* gsh  = smem + SM_G;
    float* bsh  = smem + SM_BE;
    float* dots = smem + SM_DOTS;
    float* att2 = smem + SM_ATT2;
    float* mu   = smem + SM_MU;
    float* rstd = smem + SM_RSTD;

    const uint32_t mbar = smem_u32(smem + SM_MBAR);

    // ---- Bulk-load everything this CTA needs, in one mbarrier transaction ----
    if (tid == 0) {
        mbar_init(mbar, 1);
        asm volatile("fence.proxy.async.shared::cta;" ::: "memory");
    }
    __syncthreads();
    if (tid == 0) {
        const uint32_t total = T_ * ROWB + 16384u + 4096u + 256u + 256u;
        mbar_expect_tx(mbar, total);
        const uint32_t v_s = smem_u32(v);
#pragma unroll
        for (int t = 0; t < T_; t++) {
            const float* src = x + ((size_t)(b * T_ + t) * C_ + c) * HW_;
            bulk_g2s(v_s + t * ROWB, src, ROWB, mbar);
        }
        bulk_g2s(smem_u32(Msh), g_M, 16384u, mbar);
        bulk_g2s(smem_u32(s), pos + (size_t)bc * (T_ * NTOK), 4096u, mbar);
        bulk_g2s(smem_u32(gsh), gamma, 256u, mbar);
        bulk_g2s(smem_u32(bsh), beta, 256u, mbar);
    }
    mbar_wait(mbar, 0);

    // ---- Pooling: thread (t,e) averages its 7x7 block, add to preloaded pos ----
    {
        const int t  = tid >> 6;
        const int e  = tid & 63;
        const int yi = e >> 3;
        const int xi = e & 7;
        const float* base = v + t * HW_ + (yi * 7) * 56 + xi * 7;
        float acc = 0.f;
#pragma unroll
        for (int r = 0; r < 7; r++)
#pragma unroll
            for (int cc = 0; cc < 7; cc++)
                acc += base[r * 56 + cc];
        s[tid] += acc * (1.0f / 49.0f);
    }
    __syncthreads();

    // ---- LayerNorm stats (16 rows, one thread each; rows are only 64 wide) ----
    if (tid < T_) {
        float m = 0.f, m2 = 0.f;
#pragma unroll
        for (int e = 0; e < 64; e++) {
            float xv = s[tid * 64 + e];
            m += xv; m2 = fmaf(xv, xv, m2);
        }
        m *= (1.0f / 64.0f);
        float var = m2 * (1.0f / 64.0f) - m * m;
        mu[tid] = m;
        rstd[tid] = rsqrtf(var + LN_EPS);
    }
    __syncthreads();
    {
        const int t = tid >> 6, e = tid & 63;
        s[tid] = (s[tid] - mu[t]) * rstd[t] * gsh[e] + bsh[e];
    }
    __syncthreads();

    // ---- u = s_n @ M  (16x64, one output per thread) ----
    {
        const int t = tid >> 6, e2 = tid & 63;
        float acc = 0.f;
#pragma unroll
        for (int e = 0; e < 64; e++)
            acc = fmaf(s[t * 64 + e], Msh[e * 64 + e2], acc);
        u[tid] = acc;
    }
    __syncthreads();

    // ---- dots[i][j] = scale * <u[i], s_n[j]> ----
    if (tid < 256) {
        const int i = tid >> 4, j = tid & 15;
        float acc = 0.f;
#pragma unroll
        for (int e = 0; e < 64; e++)
            acc = fmaf(u[i * 64 + e], s[j * 64 + e], acc);
        dots[tid] = acc * SCALE;
    }
    __syncthreads();

    // ---- softmax rows + pack attn into duplicated f32x2 pairs ----
    if (tid < T_) {
        float mx = -1e30f;
#pragma unroll
        for (int j = 0; j < 16; j++) mx = fmaxf(mx, dots[tid * 16 + j]);
        float ex[16], sum = 0.f;
#pragma unroll
        for (int j = 0; j < 16; j++) {
            ex[j] = __expf(dots[tid * 16 + j] - mx);
            sum += ex[j];
        }
        float inv = 1.0f / sum;
#pragma unroll
        for (int j = 0; j < 16; j++) {
            float p = ex[j] * inv;
            att2[(tid * 16 + j) * 2 + 0] = p;
            att2[(tid * 16 + j) * 2 + 1] = p;
        }
    }
    __syncthreads();

    // ---- Epilogue: out[i][f] = v[i][f] + sum_j attn[i][j] * v[j][f] ----
    // Packed f32x2: each thread owns a pair of columns per iteration.
    const unsigned long long* v64 = (const unsigned long long*)v;    // row stride 1568
    const unsigned long long* a64 = (const unsigned long long*)att2; // [i*16+j]
    const size_t outbase = ((size_t)(b * T_) * C_ + c) * HW_;

    for (int fp = tid; fp < HW_ / 2; fp += 1024) {
        unsigned long long vv[16];
#pragma unroll
        for (int j = 0; j < 16; j++)
            vv[j] = v64[j * (HW_ / 2) + fp];
#pragma unroll
        for (int i = 0; i < 16; i++) {
            unsigned long long acc = vv[i];    // residual (+x)
#pragma unroll
            for (int j = 0; j < 16; j++)
                acc = fma2(a64[i * 16 + j], vv[j], acc);
            *(unsigned long long*)(out + outbase + (size_t)i * (C_ * HW_) + fp * 2) = acc;
        }
    }
}

// ---------------------------------------------------------------------------
// Launch: inputs per metadata order: x, pos_embedding, W_qk, gamma, beta
// ---------------------------------------------------------------------------
extern "C" void kernel_launch(void* const* d_in, const int* in_sizes, int n_in,
                              void* d_out, int out_size) {
    const float* x     = (const float*)d_in[0];
    const float* pos   = (const float*)d_in[1];
    const float* W     = (const float*)d_in[2];
    const float* gamma = (const float*)d_in[3];
    const float* beta  = (const float*)d_in[4];
    float* out = (float*)d_out;

    precompute_M<<<4, 1024>>>(W);

    cudaFuncSetAttribute(cta_fused,
                         cudaFuncAttributeMaxDynamicSharedMemorySize, SMEM_BYTES);
    cta_fused<<<B_ * C_, 1024, SMEM_BYTES>>>(x, pos, gamma, beta, out);
}

// round 2
// speedup vs baseline: 2.2156x; 2.2156x over previous
#include <cuda_runtime.h>
#include <cstdint>

// Problem constants: b=8, t=16, c=64, h=w=56, DIM=8, tokens=64, DIM_HEAD=64
#define B_    8
#define T_    16
#define C_    64
#define HW_   3136
#define HW4_  784            // HW_ / 4 (float4 units)
#define LN_EPS 1e-5f
#define SCALE  0.125f

typedef unsigned long long ull;

// Global scratch (allowed: __device__ arrays)
__device__ float g_M[64 * 64];            // W_q @ W_k^T
__device__ float g_S[512 * 1024];         // pooled tokens + pos, (bc, t, 64)
__device__ ull   g_A2[512 * 256];         // attn, each value duplicated into f32x2

__device__ __forceinline__ ull fma2(ull a, ull b, ull c) {
    ull d;
    asm("fma.rn.f32x2 %0, %1, %2, %3;" : "=l"(d) : "l"(a), "l"(b), "l"(c));
    return d;
}

// ---------------------------------------------------------------------------
// K0: M = W_q @ W_k^T  (64x64). W stored (in=64, out=128): q cols [0,64), k [64,128)
// ---------------------------------------------------------------------------
__global__ void precompute_M(const float* __restrict__ W) {
    int idx = blockIdx.x * blockDim.x + threadIdx.x;   // 0..4095
    int e  = idx >> 6;
    int e2 = idx & 63;
    float acc = 0.f;
#pragma unroll
    for (int d = 0; d < 64; d++)
        acc = fmaf(W[e * 128 + d], W[e2 * 128 + 64 + d], acc);
    g_M[idx] = acc;
}

// ---------------------------------------------------------------------------
// K1: pooling. One CTA per (b,t,c) row (8192 CTAs). Stage row in SMEM,
// 64 threads each average a 7x7 block; write pooled + pos to g_S.
// g_S index = ((b*C + c)*T + t)*64 + e  (same linear layout as pos_embedding)
// ---------------------------------------------------------------------------
__global__ void __launch_bounds__(256) pool_kernel(const float* __restrict__ x,
                                                   const float* __restrict__ pos) {
    __shared__ float row[HW_];
    const int id = blockIdx.x;                  // ((b*T + t)*C + c)
    const float4* src = (const float4*)x + (size_t)id * HW4_;
    float4* r4 = (float4*)row;
    for (int i = threadIdx.x; i < HW4_; i += 256)
        r4[i] = src[i];
    __syncthreads();

    if (threadIdx.x < 64) {
        const int e  = threadIdx.x;
        const int yi = e >> 3, xi = e & 7;
        const float* bp = row + (yi * 7) * 56 + xi * 7;
        float acc = 0.f;
#pragma unroll
        for (int r = 0; r < 7; r++)
#pragma unroll
            for (int cc = 0; cc < 7; cc++)
                acc += bp[r * 56 + cc];
        const int b = id >> 10;
        const int t = (id >> 6) & 15;
        const int c = id & 63;
        const size_t o = ((size_t)((b * C_ + c) * T_ + t)) * 64 + e;
        g_S[o] = acc * (1.0f / 49.0f) + pos[o];
    }
}

// ---------------------------------------------------------------------------
// K2: per (b,c): LayerNorm -> u = s_n @ M -> dots = u s_n^T * scale -> softmax
// Writes attn as duplicated f32 pairs to g_A2.
// ---------------------------------------------------------------------------
__global__ void __launch_bounds__(256) mid_kernel(const float* __restrict__ gamma,
                                                  const float* __restrict__ beta) {
    __shared__ float s[1024], Msh[4096], u[1024];
    __shared__ float mu[16], rstd[16], dots[256], gsh[64], bsh[64];
    const int bc  = blockIdx.x;
    const int tid = threadIdx.x;

    for (int i = tid; i < 1024; i += 256) s[i] = g_S[bc * 1024 + i];
    for (int i = tid; i < 4096; i += 256) Msh[i] = g_M[i];
    if (tid < 64) { gsh[tid] = gamma[tid]; bsh[tid] = beta[tid]; }
    __syncthreads();

    if (tid < T_) {
        float m = 0.f, m2 = 0.f;
#pragma unroll
        for (int e = 0; e < 64; e++) {
            float xv = s[tid * 64 + e];
            m += xv; m2 = fmaf(xv, xv, m2);
        }
        m *= (1.0f / 64.0f);
        float var = m2 * (1.0f / 64.0f) - m * m;
        mu[tid]   = m;
        rstd[tid] = rsqrtf(var + LN_EPS);
    }
    __syncthreads();

    for (int i = tid; i < 1024; i += 256) {
        const int t = i >> 6, e = i & 63;
        s[i] = (s[i] - mu[t]) * rstd[t] * gsh[e] + bsh[e];
    }
    __syncthreads();

    for (int i = tid; i < 1024; i += 256) {
        const int t = i >> 6, e2 = i & 63;
        float acc = 0.f;
#pragma unroll
        for (int e = 0; e < 64; e++)
            acc = fmaf(s[t * 64 + e], Msh[e * 64 + e2], acc);
        u[i] = acc;
    }
    __syncthreads();

    if (tid < 256) {
        const int i = tid >> 4, j = tid & 15;
        float acc = 0.f;
#pragma unroll
        for (int e = 0; e < 64; e++)
            acc = fmaf(u[i * 64 + e], s[j * 64 + e], acc);
        dots[tid] = acc * SCALE;
    }
    __syncthreads();

    if (tid < T_) {
        float mx = -1e30f;
#pragma unroll
        for (int j = 0; j < 16; j++) mx = fmaxf(mx, dots[tid * 16 + j]);
        float ex[16], sum = 0.f;
#pragma unroll
        for (int j = 0; j < 16; j++) {
            ex[j] = __expf(dots[tid * 16 + j] - mx);
            sum += ex[j];
        }
        float inv = 1.0f / sum;
#pragma unroll
        for (int j = 0; j < 16; j++) {
            float p = ex[j] * inv;
            unsigned int ub = __float_as_uint(p);
            g_A2[bc * 256 + tid * 16 + j] = ((ull)ub << 32) | (ull)ub;
        }
    }
}

// ---------------------------------------------------------------------------
// K3: epilogue. out[b,i,c,hw] = x[b,i,c,hw] + sum_j attn[bc][i][j] x[b,j,c,hw]
// Grid (512, 2): CTA handles (b,c) and a half-row chunk of 392 float4.
// Per thread: 16 independent LDG.128, 16x16 packed f32x2 FMAs, 16 STG.128.
// ---------------------------------------------------------------------------
__global__ void __launch_bounds__(256) epilogue_kernel(const float* __restrict__ x,
                                                       float* __restrict__ out) {
    __shared__ ull a2[256];
    const int bc = blockIdx.x;
    const int b  = bc >> 6;
    const int c  = bc & 63;
    a2[threadIdx.x] = g_A2[bc * 256 + threadIdx.x];
    __syncthreads();

    const size_t rowbase = ((size_t)(b * T_) * C_ + c) * HW4_;   // float4 units
    const size_t rstride = (size_t)C_ * HW4_;                    // row j stride

#pragma unroll
    for (int k = 0; k < 2; k++) {
        const int rel = k * 256 + (int)threadIdx.x;
        if (rel < 392) {
            const int f = blockIdx.y * 392 + rel;
            ulonglong2 vv[16];
#pragma unroll
            for (int j = 0; j < 16; j++)
                vv[j] = *(const ulonglong2*)((const float4*)x + rowbase + (size_t)j * rstride + f);
#pragma unroll
            for (int i = 0; i < 16; i++) {
                ulonglong2 acc = vv[i];           // residual (+x)
#pragma unroll
                for (int j = 0; j < 16; j++) {
                    const ull a = a2[i * 16 + j];
                    acc.x = fma2(a, vv[j].x, acc.x);
                    acc.y = fma2(a, vv[j].y, acc.y);
                }
                *(ulonglong2*)((float4*)out + rowbase + (size_t)i * rstride + f) = acc;
            }
        }
    }
}

// ---------------------------------------------------------------------------
// Launch. Inputs: x, pos_embedding, W_qk, gamma, beta
// ---------------------------------------------------------------------------
extern "C" void kernel_launch(void* const* d_in, const int* in_sizes, int n_in,
                              void* d_out, int out_size) {
    const float* x     = (const float*)d_in[0];
    const float* pos   = (const float*)d_in[1];
    const float* W     = (const float*)d_in[2];
    const float* gamma = (const float*)d_in[3];
    const float* beta  = (const float*)d_in[4];
    float* out = (float*)d_out;

    precompute_M<<<4, 1024>>>(W);
    pool_kernel<<<B_ * T_ * C_, 256>>>(x, pos);
    mid_kernel<<<B_ * C_, 256>>>(gamma, beta);
    dim3 egrid(B_ * C_, 2);
    epilogue_kernel<<<egrid, 256>>>(x, out);
}

// round 3
// speedup vs baseline: 4.6022x; 2.0772x over previous
#include <cuda_runtime.h>
#include <cstdint>

// Problem constants: b=8, t=16, c=64, h=w=56, DIM=8, tokens=64, DIM_HEAD=64
#define B_    8
#define T_    16
#define C_    64
#define HW_   3136
#define HW4_  784            // HW_ / 4 (float4 units)
#define HW2_  1568           // HW_ / 2 (float2 / ull units)
#define LN_EPS 1e-5f
#define SCALE  0.125f

typedef unsigned long long ull;

// Global scratch
__device__ float g_M[64 * 64];            // W_q @ W_k^T
__device__ float g_S[512 * 1024];         // pooled tokens + pos, (bc, t, 64)
__device__ ull   g_A2[512 * 256];         // attn, duplicated into f32x2 pairs

__device__ __forceinline__ ull fma2(ull a, ull b, ull c) {
    ull d;
    asm("fma.rn.f32x2 %0, %1, %2, %3;" : "=l"(d) : "l"(a), "l"(b), "l"(c));
    return d;
}

// ---------------------------------------------------------------------------
// K0: M = W_q @ W_k^T  (64x64). W stored (in=64, out=128): q cols [0,64), k [64,128)
// ---------------------------------------------------------------------------
__global__ void precompute_M(const float* __restrict__ W) {
    int idx = blockIdx.x * blockDim.x + threadIdx.x;   // 0..4095
    int e  = idx >> 6;
    int e2 = idx & 63;
    float acc = 0.f;
#pragma unroll
    for (int d = 0; d < 64; d++)
        acc = fmaf(W[e * 128 + d], W[e2 * 128 + 64 + d], acc);
    g_M[idx] = acc;
}

// ---------------------------------------------------------------------------
// K1: pooling. One CTA per (b,t,c) row. Stage row in SMEM (coalesced float4),
// 64 threads each average a 7x7 block; write pooled + pos to g_S.
// g_S index = ((b*C + c)*T + t)*64 + e
// ---------------------------------------------------------------------------
__global__ void __launch_bounds__(256) pool_kernel(const float* __restrict__ x,
                                                   const float* __restrict__ pos) {
    __shared__ float row[HW_];
    const int id = blockIdx.x;                  // ((b*T + t)*C + c)
    const float4* src = (const float4*)x + (size_t)id * HW4_;
    float4* r4 = (float4*)row;
#pragma unroll 4
    for (int i = threadIdx.x; i < HW4_; i += 256)
        r4[i] = src[i];
    __syncthreads();

    if (threadIdx.x < 64) {
        const int e  = threadIdx.x;
        const int yi = e >> 3, xi = e & 7;
        const float* bp = row + (yi * 7) * 56 + xi * 7;
        float acc = 0.f;
#pragma unroll
        for (int r = 0; r < 7; r++)
#pragma unroll
            for (int cc = 0; cc < 7; cc++)
                acc += bp[r * 56 + cc];
        const int b = id >> 10;
        const int t = (id >> 6) & 15;
        const int c = id & 63;
        const size_t o = ((size_t)((b * C_ + c) * T_ + t)) * 64 + e;
        g_S[o] = acc * (1.0f / 49.0f) + pos[o];
    }
}

// ---------------------------------------------------------------------------
// K2: per (b,c): LayerNorm -> u = s_n @ M -> dots -> softmax -> g_A2
// ---------------------------------------------------------------------------
__global__ void __launch_bounds__(256) mid_kernel(const float* __restrict__ gamma,
                                                  const float* __restrict__ beta) {
    __shared__ float s[1024], Msh[4096], u[1024];
    __shared__ float mu[16], rstd[16], dots[256], gsh[64], bsh[64];
    const int bc  = blockIdx.x;
    const int tid = threadIdx.x;

    for (int i = tid; i < 1024; i += 256) s[i] = g_S[bc * 1024 + i];
    for (int i = tid; i < 4096; i += 256) Msh[i] = g_M[i];
    if (tid < 64) { gsh[tid] = gamma[tid]; bsh[tid] = beta[tid]; }
    __syncthreads();

    if (tid < T_) {
        float m = 0.f, m2 = 0.f;
#pragma unroll
        for (int e = 0; e < 64; e++) {
            float xv = s[tid * 64 + e];
            m += xv; m2 = fmaf(xv, xv, m2);
        }
        m *= (1.0f / 64.0f);
        float var = m2 * (1.0f / 64.0f) - m * m;
        mu[tid]   = m;
        rstd[tid] = rsqrtf(var + LN_EPS);
    }
    __syncthreads();

    for (int i = tid; i < 1024; i += 256) {
        const int t = i >> 6, e = i & 63;
        s[i] = (s[i] - mu[t]) * rstd[t] * gsh[e] + bsh[e];
    }
    __syncthreads();

    for (int i = tid; i < 1024; i += 256) {
        const int t = i >> 6, e2 = i & 63;
        float acc = 0.f;
#pragma unroll
        for (int e = 0; e < 64; e++)
            acc = fmaf(s[t * 64 + e], Msh[e * 64 + e2], acc);
        u[i] = acc;
    }
    __syncthreads();

    if (tid < 256) {
        const int i = tid >> 4, j = tid & 15;
        float acc = 0.f;
#pragma unroll
        for (int e = 0; e < 64; e++)
            acc = fmaf(u[i * 64 + e], s[j * 64 + e], acc);
        dots[tid] = acc * SCALE;
    }
    __syncthreads();

    if (tid < T_) {
        float mx = -1e30f;
#pragma unroll
        for (int j = 0; j < 16; j++) mx = fmaxf(mx, dots[tid * 16 + j]);
        float ex[16], sum = 0.f;
#pragma unroll
        for (int j = 0; j < 16; j++) {
            ex[j] = __expf(dots[tid * 16 + j] - mx);
            sum += ex[j];
        }
        float inv = 1.0f / sum;
#pragma unroll
        for (int j = 0; j < 16; j++) {
            float p = ex[j] * inv;
            unsigned int ub = __float_as_uint(p);
            g_A2[bc * 256 + tid * 16 + j] = ((ull)ub << 32) | (ull)ub;
        }
    }
}

// ---------------------------------------------------------------------------
// K3: epilogue. out[b,i,c,hw] = x[b,i,c,hw] + sum_j attn[bc][i][j] x[b,j,c,hw]
// Grid (512, 7) x 224 threads. Each thread owns ONE 8-byte column pair:
//   vv[16] = 32 regs -> no spill. 16 coalesced LDG.64, 256 fma2, 16 STG.64.
// ---------------------------------------------------------------------------
__global__ void __launch_bounds__(224) epilogue_kernel(const float* __restrict__ x,
                                                       float* __restrict__ out) {
    __shared__ ull a2[256];
    const int bc = blockIdx.x;
    const int b  = bc >> 6;
    const int c  = bc & 63;
    for (int i = threadIdx.x; i < 256; i += 224)
        a2[i] = g_A2[bc * 256 + i];
    __syncthreads();

    const int f = blockIdx.y * 224 + threadIdx.x;          // 0..1567 (ull units)
    const size_t rowbase = ((size_t)(b * T_) * C_ + c) * HW2_;   // ull units
    const size_t rstride = (size_t)C_ * HW2_;              // t stride (ull units)
    const ull* xin = (const ull*)x + rowbase + f;
    ull*       xo  = (ull*)out + rowbase + f;

    ull vv[16];
#pragma unroll
    for (int j = 0; j < 16; j++)
        vv[j] = xin[(size_t)j * rstride];

#pragma unroll
    for (int i = 0; i < 16; i++) {
        ull acc = vv[i];                                   // residual (+x)
#pragma unroll
        for (int j = 0; j < 16; j++)
            acc = fma2(a2[i * 16 + j], vv[j], acc);
        xo[(size_t)i * rstride] = acc;
    }
}

// ---------------------------------------------------------------------------
// Launch. Inputs: x, pos_embedding, W_qk, gamma, beta
// ---------------------------------------------------------------------------
extern "C" void kernel_launch(void* const* d_in, const int* in_sizes, int n_in,
                              void* d_out, int out_size) {
    const float* x     = (const float*)d_in[0];
    const float* pos   = (const float*)d_in[1];
    const float* W     = (const float*)d_in[2];
    const float* gamma = (const float*)d_in[3];
    const float* beta  = (const float*)d_in[4];
    float* out = (float*)d_out;

    precompute_M<<<4, 1024>>>(W);
    pool_kernel<<<B_ * T_ * C_, 256>>>(x, pos);
    mid_kernel<<<B_ * C_, 256>>>(gamma, beta);
    dim3 egrid(B_ * C_, 7);
    epilogue_kernel<<<egrid, 224>>>(x, out);
}

// round 7
// speedup vs baseline: 4.9039x; 1.0656x over previous
#include <cuda_runtime.h>
#include <cstdint>

// Problem constants: b=8, t=16, c=64, h=w=56, DIM=8, tokens=64, DIM_HEAD=64
#define B_    8
#define T_    16
#define C_    64
#define HW_   3136
#define HW4_  784            // HW_ / 4 (float4 units)
#define LN_EPS 1e-5f
#define SCALE  0.125f

typedef unsigned long long ull;

// Global scratch
__device__ float g_M[64 * 64];            // W_q @ W_k^T
__device__ float g_S[512 * 1024];         // pooled tokens + pos, (bc, t, 64)
__device__ ull   g_A2[512 * 256];         // attn, duplicated into f32x2 pairs

__device__ __forceinline__ ull fma2(ull a, ull b, ull c) {
    ull d;
    asm("fma.rn.f32x2 %0, %1, %2, %3;" : "=l"(d) : "l"(a), "l"(b), "l"(c));
    return d;
}

// ---------------------------------------------------------------------------
// K1: pooling (blocks 0..8191) + M precompute (blocks 8192..8195).
// Pool: one CTA per (b,t,c) row. Stage row in SMEM, 64 threads average
// 7x7 blocks, write pooled+pos to g_S[((b*C+c)*T+t)*64 + e].
// M: M[e][e2] = sum_d W[e][d]*W[e2][64+d]  (W stored (in=64, out=128))
// ---------------------------------------------------------------------------
__global__ void __launch_bounds__(128) pool_kernel(const float* __restrict__ x,
                                                   const float* __restrict__ pos,
                                                   const float* __restrict__ W) {
    if (blockIdx.x >= 8192) {
        const int base = (blockIdx.x - 8192) * 1024 + threadIdx.x;
#pragma unroll
        for (int k = 0; k < 8; k++) {
            const int idx = base + k * 128;
            const int e = idx >> 6, e2 = idx & 63;
            float acc = 0.f;
#pragma unroll
            for (int d = 0; d < 64; d++)
                acc = fmaf(W[e * 128 + d], W[e2 * 128 + 64 + d], acc);
            g_M[idx] = acc;
        }
        return;
    }

    __shared__ float row[HW_];
    const int id = blockIdx.x;                  // ((b*T + t)*C + c)
    const float4* src = (const float4*)x + (size_t)id * HW4_;
    float4* r4 = (float4*)row;
#pragma unroll 7
    for (int i = threadIdx.x; i < HW4_; i += 128)
        r4[i] = src[i];
    __syncthreads();

    if (threadIdx.x < 64) {
        const int e  = threadIdx.x;
        const int yi = e >> 3, xi = e & 7;
        const float* bp = row + (yi * 7) * 56 + xi * 7;
        float acc = 0.f;
#pragma unroll
        for (int r = 0; r < 7; r++)
#pragma unroll
            for (int cc = 0; cc < 7; cc++)
                acc += bp[r * 56 + cc];
        const int b = id >> 10;
        const int t = (id >> 6) & 15;
        const int c = id & 63;
        const size_t o = ((size_t)((b * C_ + c) * T_ + t)) * 64 + e;
        g_S[o] = acc * (1.0f / 49.0f) + pos[o];
    }
}

// ---------------------------------------------------------------------------
// K2: per (b,c): LayerNorm -> u = s_n @ M -> dots -> softmax -> g_A2
// ---------------------------------------------------------------------------
__global__ void __launch_bounds__(256) mid_kernel(const float* __restrict__ gamma,
                                                  const float* __restrict__ beta) {
    __shared__ float s[1024], Msh[4096], u[1024];
    __shared__ float mu[16], rstd[16], dots[256], gsh[64], bsh[64];
    const int bc  = blockIdx.x;
    const int tid = threadIdx.x;

    for (int i = tid; i < 1024; i += 256) s[i] = g_S[bc * 1024 + i];
    for (int i = tid; i < 4096; i += 256) Msh[i] = g_M[i];
    if (tid < 64) { gsh[tid] = gamma[tid]; bsh[tid] = beta[tid]; }
    __syncthreads();

    if (tid < T_) {
        float m = 0.f, m2 = 0.f;
#pragma unroll
        for (int e = 0; e < 64; e++) {
            float xv = s[tid * 64 + e];
            m += xv; m2 = fmaf(xv, xv, m2);
        }
        m *= (1.0f / 64.0f);
        float var = m2 * (1.0f / 64.0f) - m * m;
        mu[tid]   = m;
        rstd[tid] = rsqrtf(var + LN_EPS);
    }
    __syncthreads();

    for (int i = tid; i < 1024; i += 256) {
        const int t = i >> 6, e = i & 63;
        s[i] = (s[i] - mu[t]) * rstd[t] * gsh[e] + bsh[e];
    }
    __syncthreads();

    for (int i = tid; i < 1024; i += 256) {
        const int t = i >> 6, e2 = i & 63;
        float acc = 0.f;
#pragma unroll
        for (int e = 0; e < 64; e++)
            acc = fmaf(s[t * 64 + e], Msh[e * 64 + e2], acc);
        u[i] = acc;
    }
    __syncthreads();

    if (tid < 256) {
        const int i = tid >> 4, j = tid & 15;
        float acc = 0.f;
#pragma unroll
        for (int e = 0; e < 64; e++)
            acc = fmaf(u[i * 64 + e], s[j * 64 + e], acc);
        dots[tid] = acc * SCALE;
    }
    __syncthreads();

    if (tid < T_) {
        float mx = -1e30f;
#pragma unroll
        for (int j = 0; j < 16; j++) mx = fmaxf(mx, dots[tid * 16 + j]);
        float ex[16], sum = 0.f;
#pragma unroll
        for (int j = 0; j < 16; j++) {
            ex[j] = __expf(dots[tid * 16 + j] - mx);
            sum += ex[j];
        }
        float inv = 1.0f / sum;
#pragma unroll
        for (int j = 0; j < 16; j++) {
            float p = ex[j] * inv;
            unsigned int ub = __float_as_uint(p);
            g_A2[bc * 256 + tid * 16 + j] = ((ull)ub << 32) | (ull)ub;
        }
    }
}

// ---------------------------------------------------------------------------
// K3: epilogue. out[b,i,c,hw] = x[b,i,c,hw] + sum_j attn[bc][i][j] x[b,j,c,hw]
// Grid (512, 4) x 196 threads: each thread owns ONE float4 column
// (f4 = blockIdx.y*196 + tid in [0,784)). 16 LDG.128, 16x8 LDS.128 of attn
// pairs, each a2 value feeds both packed halves; 16 STG.128.
// ---------------------------------------------------------------------------
__global__ void __launch_bounds__(196) epilogue_kernel(const float* __restrict__ x,
                                                       float* __restrict__ out) {
    __shared__ __align__(16) ull a2[256];
    const int bc = blockIdx.x;
    const int b  = bc >> 6;
    const int c  = bc & 63;
    for (int i = threadIdx.x; i < 256; i += 196)
        a2[i] = g_A2[bc * 256 + i];
    __syncthreads();

    const int f4 = blockIdx.y * 196 + threadIdx.x;             // 0..783 float4 cols
    const size_t rowbase = ((size_t)(b * T_) * C_ + c) * HW4_; // float4 units
    const size_t rstride = (size_t)C_ * HW4_;                  // t stride (float4)
    const ulonglong2* xin = (const ulonglong2*)((const float4*)x + rowbase + f4);
    ulonglong2*       xo  = (ulonglong2*)((float4*)out + rowbase + f4);

    ulonglong2 vv[16];
#pragma unroll
    for (int j = 0; j < 16; j++)
        vv[j] = xin[(size_t)j * rstride];

    const ulonglong2* a2v = (const ulonglong2*)a2;
#pragma unroll
    for (int i = 0; i < 16; i++) {
        ulonglong2 acc = vv[i];                                // residual (+x)
#pragma unroll
        for (int jj = 0; jj < 8; jj++) {
            const ulonglong2 ap = a2v[i * 8 + jj];
            acc.x = fma2(ap.x, vv[2 * jj].x,     acc.x);
            acc.y = fma2(ap.x, vv[2 * jj].y,     acc.y);
            acc.x = fma2(ap.y, vv[2 * jj + 1].x, acc.x);
            acc.y = fma2(ap.y, vv[2 * jj + 1].y, acc.y);
        }
        xo[(size_t)i * rstride] = acc;
    }
}

// ---------------------------------------------------------------------------
// Launch. Inputs: x, pos_embedding, W_qk, gamma, beta
// ---------------------------------------------------------------------------
extern "C" void kernel_launch(void* const* d_in, const int* in_sizes, int n_in,
                              void* d_out, int out_size) {
    const float* x     = (const float*)d_in[0];
    const float* pos   = (const float*)d_in[1];
    const float* W     = (const float*)d_in[2];
    const float* gamma = (const float*)d_in[3];
    const float* beta  = (const float*)d_in[4];
    float* out = (float*)d_out;

    pool_kernel<<<B_ * T_ * C_ + 4, 128>>>(x, pos, W);
    mid_kernel<<<B_ * C_, 256>>>(gamma, beta);
    dim3 egrid(B_ * C_, 4);
    epilogue_kernel<<<egrid, 196>>>(x, out);
}

// round 8
// speedup vs baseline: 4.9740x; 1.0143x over previous
#include <cuda_runtime.h>
#include <cstdint>

// Problem constants: b=8, t=16, c=64, h=w=56, DIM=8, tokens=64, DIM_HEAD=64
#define B_    8
#define T_    16
#define C_    64
#define HW_   3136
#define HW4_  784            // HW_ / 4 (float4 units)
#define LN_EPS 1e-5f
#define SCALE  0.125f

typedef unsigned long long ull;

// Global scratch
__device__ float g_M[64 * 64];            // W_q @ W_k^T
__device__ float g_S[512 * 1024];         // pooled tokens + pos, (bc, t, 64)
__device__ ull   g_A2[512 * 256];         // attn, duplicated into f32x2 pairs

__device__ __forceinline__ ull fma2(ull a, ull b, ull c) {
    ull d;
    asm("fma.rn.f32x2 %0, %1, %2, %3;" : "=l"(d) : "l"(a), "l"(b), "l"(c));
    return d;
}

// ---------------------------------------------------------------------------
// K0: M = W_q @ W_k^T  (64x64). W stored (in=64, out=128): q cols [0,64), k [64,128)
// ---------------------------------------------------------------------------
__global__ void precompute_M(const float* __restrict__ W) {
    int idx = blockIdx.x * blockDim.x + threadIdx.x;   // 0..4095
    int e  = idx >> 6;
    int e2 = idx & 63;
    float acc = 0.f;
#pragma unroll
    for (int d = 0; d < 64; d++)
        acc = fmaf(W[e * 128 + d], W[e2 * 128 + 64 + d], acc);
    g_M[idx] = acc;
}

// ---------------------------------------------------------------------------
// K1: pooling, separable. Grid 4096 x 224 threads; CTA handles 2 ids.
// Phase 1: thread (sub,yi,c4) sums 7 grid rows of one float4 column group
//          (7 independent coalesced LDG.128, stride 224B) -> SMEM colsum.
// Phase 2: thread (sub,e) sums 7 colsum floats (stride 7, conflict-free),
//          scales by 1/49, adds pos, stores g_S[((b*C+c)*T+t)*64 + e].
// ---------------------------------------------------------------------------
__global__ void __launch_bounds__(224) pool_kernel(const float* __restrict__ x,
                                                   const float* __restrict__ pos) {
    __shared__ float colsum[2][448];          // 2 ids x (8 yi x 56 cols)
    const int tid = threadIdx.x;
    const int id0 = blockIdx.x * 2;

    {
        const int sub = tid / 112;            // which id
        const int st  = tid % 112;            // 0..111
        const int yi  = st / 14;              // pooled row 0..7
        const int c4  = st % 14;              // float4 col group 0..13
        const float4* src = (const float4*)x
            + (size_t)(id0 + sub) * HW4_ + (yi * 7) * 14 + c4;
        float4 a = src[0];
#pragma unroll
        for (int r = 1; r < 7; r++) {
            const float4 v = src[r * 14];
            a.x += v.x; a.y += v.y; a.z += v.z; a.w += v.w;
        }
        *(float4*)&colsum[sub][yi * 56 + c4 * 4] = a;
    }
    __syncthreads();

    if (tid < 128) {
        const int sub = tid >> 6;
        const int e   = tid & 63;
        const int yi  = e >> 3, xi = e & 7;
        const float* cp = &colsum[sub][yi * 56 + xi * 7];
        float acc = cp[0] + cp[1] + cp[2] + cp[3] + cp[4] + cp[5] + cp[6];
        const int id = id0 + sub;             // (b*T + t)*C + c
        const int b = id >> 10;
        const int t = (id >> 6) & 15;
        const int c = id & 63;
        const size_t o = ((size_t)((b * C_ + c) * T_ + t)) * 64 + e;
        g_S[o] = acc * (1.0f / 49.0f) + pos[o];
    }
}

// ---------------------------------------------------------------------------
// K2: per (b,c): LayerNorm -> u = s_n @ M -> dots -> softmax -> g_A2
// ---------------------------------------------------------------------------
__global__ void __launch_bounds__(256) mid_kernel(const float* __restrict__ gamma,
                                                  const float* __restrict__ beta) {
    __shared__ float s[1024], Msh[4096], u[1024];
    __shared__ float mu[16], rstd[16], dots[256], gsh[64], bsh[64];
    const int bc  = blockIdx.x;
    const int tid = threadIdx.x;

    for (int i = tid; i < 1024; i += 256) s[i] = g_S[bc * 1024 + i];
    for (int i = tid; i < 4096; i += 256) Msh[i] = g_M[i];
    if (tid < 64) { gsh[tid] = gamma[tid]; bsh[tid] = beta[tid]; }
    __syncthreads();

    if (tid < T_) {
        float m = 0.f, m2 = 0.f;
#pragma unroll
        for (int e = 0; e < 64; e++) {
            float xv = s[tid * 64 + e];
            m += xv; m2 = fmaf(xv, xv, m2);
        }
        m *= (1.0f / 64.0f);
        float var = m2 * (1.0f / 64.0f) - m * m;
        mu[tid]   = m;
        rstd[tid] = rsqrtf(var + LN_EPS);
    }
    __syncthreads();

    for (int i = tid; i < 1024; i += 256) {
        const int t = i >> 6, e = i & 63;
        s[i] = (s[i] - mu[t]) * rstd[t] * gsh[e] + bsh[e];
    }
    __syncthreads();

    for (int i = tid; i < 1024; i += 256) {
        const int t = i >> 6, e2 = i & 63;
        float acc = 0.f;
#pragma unroll
        for (int e = 0; e < 64; e++)
            acc = fmaf(s[t * 64 + e], Msh[e * 64 + e2], acc);
        u[i] = acc;
    }
    __syncthreads();

    if (tid < 256) {
        const int i = tid >> 4, j = tid & 15;
        float acc = 0.f;
#pragma unroll
        for (int e = 0; e < 64; e++)
            acc = fmaf(u[i * 64 + e], s[j * 64 + e], acc);
        dots[tid] = acc * SCALE;
    }
    __syncthreads();

    if (tid < T_) {
        float mx = -1e30f;
#pragma unroll
        for (int j = 0; j < 16; j++) mx = fmaxf(mx, dots[tid * 16 + j]);
        float ex[16], sum = 0.f;
#pragma unroll
        for (int j = 0; j < 16; j++) {
            ex[j] = __expf(dots[tid * 16 + j] - mx);
            sum += ex[j];
        }
        float inv = 1.0f / sum;
#pragma unroll
        for (int j = 0; j < 16; j++) {
            float p = ex[j] * inv;
            unsigned int ub = __float_as_uint(p);
            g_A2[bc * 256 + tid * 16 + j] = ((ull)ub << 32) | (ull)ub;
        }
    }
}

// ---------------------------------------------------------------------------
// K3: epilogue. out[b,i,c,hw] = x[b,i,c,hw] + sum_j attn[bc][i][j] x[b,j,c,hw]
// Grid (512, 4) x 196 threads: each thread owns ONE float4 column
// (f4 = blockIdx.y*196 + tid in [0,784)). 16 LDG.128, LDS.128 attn pairs.
// ---------------------------------------------------------------------------
__global__ void __launch_bounds__(196) epilogue_kernel(const float* __restrict__ x,
                                                       float* __restrict__ out) {
    __shared__ __align__(16) ull a2[256];
    const int bc = blockIdx.x;
    const int b  = bc >> 6;
    const int c  = bc & 63;
    for (int i = threadIdx.x; i < 256; i += 196)
        a2[i] = g_A2[bc * 256 + i];
    __syncthreads();

    const int f4 = blockIdx.y * 196 + threadIdx.x;             // 0..783 float4 cols
    const size_t rowbase = ((size_t)(b * T_) * C_ + c) * HW4_; // float4 units
    const size_t rstride = (size_t)C_ * HW4_;                  // t stride (float4)
    const ulonglong2* xin = (const ulonglong2*)((const float4*)x + rowbase + f4);
    ulonglong2*       xo  = (ulonglong2*)((float4*)out + rowbase + f4);

    ulonglong2 vv[16];
#pragma unroll
    for (int j = 0; j < 16; j++)
        vv[j] = xin[(size_t)j * rstride];

    const ulonglong2* a2v = (const ulonglong2*)a2;
#pragma unroll
    for (int i = 0; i < 16; i++) {
        ulonglong2 acc = vv[i];                                // residual (+x)
#pragma unroll
        for (int jj = 0; jj < 8; jj++) {
            const ulonglong2 ap = a2v[i * 8 + jj];
            acc.x = fma2(ap.x, vv[2 * jj].x,     acc.x);
            acc.y = fma2(ap.x, vv[2 * jj].y,     acc.y);
            acc.x = fma2(ap.y, vv[2 * jj + 1].x, acc.x);
            acc.y = fma2(ap.y, vv[2 * jj + 1].y, acc.y);
        }
        xo[(size_t)i * rstride] = acc;
    }
}

// ---------------------------------------------------------------------------
// Launch. Inputs: x, pos_embedding, W_qk, gamma, beta
// ---------------------------------------------------------------------------
extern "C" void kernel_launch(void* const* d_in, const int* in_sizes, int n_in,
                              void* d_out, int out_size) {
    const float* x     = (const float*)d_in[0];
    const float* pos   = (const float*)d_in[1];
    const float* W     = (const float*)d_in[2];
    const float* gamma = (const float*)d_in[3];
    const float* beta  = (const float*)d_in[4];
    float* out = (float*)d_out;

    precompute_M<<<4, 1024>>>(W);
    pool_kernel<<<(B_ * T_ * C_) / 2, 224>>>(x, pos);
    mid_kernel<<<B_ * C_, 256>>>(gamma, beta);
    dim3 egrid(B_ * C_, 4);
    epilogue_kernel<<<egrid, 196>>>(x, out);
}